// round 8
// baseline (speedup 1.0000x reference)
#include <cuda_runtime.h>
#include <cstdint>
#include <cstddef>

#define DI __device__ __forceinline__

// ---------------------------------------------------------------------------
// Problem constants
// ---------------------------------------------------------------------------
namespace {
constexpr int B_   = 64;
constexpr int S_   = 2048;
constexpr int F_   = 40;
constexpr int EMB_ = 128;
constexpr int HID_ = 256;
constexpr int G_   = 4 * HID_;             // 1024 gate rows
constexpr long long MS = (long long)B_ * S_;   // 131072 flattened rows

constexpr int BPC  = 4;                    // batches per cluster
constexpr int NTHR = 512;                  // threads per CTA
// dynamic smem: [2][BPC][HID] h double-buffer + [NKS][ROWS][BPC] partials
constexpr size_t REC_SMEM = (2 * BPC * HID_ + NTHR * BPC) * sizeof(float);  // 16 KB
}

// ---------------------------------------------------------------------------
// Scratch (device globals: no runtime allocation allowed)
// ---------------------------------------------------------------------------
__device__ float g_gx[(size_t)MS * G_];     // 536 MB: gate preactivations (reused L0/L1)
__device__ float g_hs[(size_t)MS * HID_];   // 134 MB: hidden states (reused L0/L1)
__device__ float g_Wc[G_ * F_];             // fused W_ih0 @ W_in
__device__ float g_b0[G_];                  // fused layer-0 bias
__device__ float g_b1[G_];                  // layer-1 bias

// ---------------------------------------------------------------------------
// f32x2 helpers (packed dual-FMA; ptxas won't emit from C++)
// ---------------------------------------------------------------------------
DI void ffma2(unsigned long long& acc, unsigned long long a, unsigned long long b) {
    asm("fma.rn.f32x2 %0, %1, %2, %0;" : "+l"(acc) : "l"(a), "l"(b));
}
DI unsigned long long dup2(float x) {
    unsigned long long d;
    unsigned u = __float_as_uint(x);
    asm("mov.b64 %0, {%1, %1};" : "=l"(d) : "r"(u));
    return d;
}
DI float lo2(unsigned long long v) { return __uint_as_float((unsigned)v); }
DI float hi2(unsigned long long v) { return __uint_as_float((unsigned)(v >> 32)); }

DI uint32_t s2u(const void* p) {
    uint32_t a;
    asm("{ .reg .u64 t; cvta.to.shared.u64 t, %1; cvt.u32.u64 %0, t; }"
        : "=r"(a) : "l"(p));
    return a;
}
DI void cluster_sync() {
    asm volatile("barrier.cluster.arrive.aligned;" ::: "memory");
    asm volatile("barrier.cluster.wait.aligned;" ::: "memory");
}

// Fast activations: EX2/RCP approx, saturation-safe at +/-inf.
DI float fex2(float x) { float y; asm("ex2.approx.f32 %0, %1;" : "=f"(y) : "f"(x)); return y; }
DI float frcp(float x) { float y; asm("rcp.approx.f32 %0, %1;" : "=f"(y) : "f"(x)); return y; }
constexpr float LOG2E_ = 1.4426950408889634f;
DI float sigf(float x)     { return frcp(1.f + fex2(-x * LOG2E_)); }
DI float tanhfast(float x) { return 1.f - 2.f * frcp(1.f + fex2(x * (2.f * LOG2E_))); }

// ---------------------------------------------------------------------------
// Prep: Wc = W_ih0 @ W_in  (1024 x 40), fused biases
// ---------------------------------------------------------------------------
__global__ void prep_kernel(const float* __restrict__ Wih0, const float* __restrict__ Win,
                            const float* __restrict__ bin,
                            const float* __restrict__ bih0, const float* __restrict__ bhh0,
                            const float* __restrict__ bih1, const float* __restrict__ bhh1) {
    int idx = blockIdx.x * blockDim.x + threadIdx.x;
    if (idx < G_ * F_) {
        int g = idx / F_, f = idx % F_;
        float s = 0.f;
        #pragma unroll 8
        for (int e = 0; e < EMB_; e++) s += Wih0[g * EMB_ + e] * Win[e * F_ + f];
        g_Wc[idx] = s;
    }
    if (idx < G_) {
        float s = bih0[idx] + bhh0[idx];
        #pragma unroll 8
        for (int e = 0; e < EMB_; e++) s += Wih0[idx * EMB_ + e] * bin[e];
        g_b0[idx] = s;
        g_b1[idx] = bih1[idx] + bhh1[idx];
    }
}

// No-op kernel: keeps the ncu capture slot aligned on lstm_rec.
__global__ void noop_kernel() {}

// ---------------------------------------------------------------------------
// GEMM: C[M][N] = A[M][K] @ Bt[N][K] + bias[N]
// 128x128 tile, 256 threads, 8x8 per thread (f32x2 on M-pairs). K % 8 == 0.
// ---------------------------------------------------------------------------
__global__ __launch_bounds__(256) void gemm_bias_f32(
    const float* __restrict__ A, const float* __restrict__ Bt,
    const float* __restrict__ bias, float* __restrict__ C, int K, int N) {
    __shared__ float As[8][128];   // [k][m]
    __shared__ float Bs[8][128];   // [k][n]

    const int tid = threadIdx.x;
    const int m0 = blockIdx.y * 128, n0 = blockIdx.x * 128;
    const int lr = tid >> 1, lq = tid & 1;
    const int ty = tid >> 4, tx = tid & 15;

    unsigned long long acc[4][8];
    #pragma unroll
    for (int i = 0; i < 4; i++)
        #pragma unroll
        for (int j = 0; j < 8; j++) acc[i][j] = 0ull;

    for (int kc = 0; kc < K; kc += 8) {
        float4 av = *(const float4*)(A + (size_t)(m0 + lr) * K + kc + lq * 4);
        float4 bv = *(const float4*)(Bt + (size_t)(n0 + lr) * K + kc + lq * 4);
        __syncthreads();
        As[lq * 4 + 0][lr] = av.x; As[lq * 4 + 1][lr] = av.y;
        As[lq * 4 + 2][lr] = av.z; As[lq * 4 + 3][lr] = av.w;
        Bs[lq * 4 + 0][lr] = bv.x; Bs[lq * 4 + 1][lr] = bv.y;
        Bs[lq * 4 + 2][lr] = bv.z; Bs[lq * 4 + 3][lr] = bv.w;
        __syncthreads();
        #pragma unroll
        for (int k = 0; k < 8; k++) {
            ulonglong2 a01 = *(const ulonglong2*)&As[k][ty * 8];
            ulonglong2 a23 = *(const ulonglong2*)&As[k][ty * 8 + 4];
            float4 bl = *(const float4*)&Bs[k][tx * 8];
            float4 bh = *(const float4*)&Bs[k][tx * 8 + 4];
            unsigned long long ap[4] = { a01.x, a01.y, a23.x, a23.y };
            unsigned long long bd[8] = { dup2(bl.x), dup2(bl.y), dup2(bl.z), dup2(bl.w),
                                         dup2(bh.x), dup2(bh.y), dup2(bh.z), dup2(bh.w) };
            #pragma unroll
            for (int mp = 0; mp < 4; mp++)
                #pragma unroll
                for (int j = 0; j < 8; j++)
                    ffma2(acc[mp][j], ap[mp], bd[j]);
        }
    }

    float bv[8];
    #pragma unroll
    for (int j = 0; j < 8; j++) bv[j] = bias[n0 + tx * 8 + j];

    #pragma unroll
    for (int mp = 0; mp < 4; mp++) {
        int m = m0 + ty * 8 + mp * 2;
        float4 r0a = { lo2(acc[mp][0]) + bv[0], lo2(acc[mp][1]) + bv[1],
                       lo2(acc[mp][2]) + bv[2], lo2(acc[mp][3]) + bv[3] };
        float4 r0b = { lo2(acc[mp][4]) + bv[4], lo2(acc[mp][5]) + bv[5],
                       lo2(acc[mp][6]) + bv[6], lo2(acc[mp][7]) + bv[7] };
        float4 r1a = { hi2(acc[mp][0]) + bv[0], hi2(acc[mp][1]) + bv[1],
                       hi2(acc[mp][2]) + bv[2], hi2(acc[mp][3]) + bv[3] };
        float4 r1b = { hi2(acc[mp][4]) + bv[4], hi2(acc[mp][5]) + bv[5],
                       hi2(acc[mp][6]) + bv[6], hi2(acc[mp][7]) + bv[7] };
        float* c0 = C + (size_t)m * N + n0 + tx * 8;
        float* c1 = c0 + N;
        *(float4*)c0 = r0a;       *(float4*)(c0 + 4) = r0b;
        *(float4*)c1 = r1a;       *(float4*)(c1 + 4) = r1b;
    }
}

// ---------------------------------------------------------------------------
// LSTM recurrence v5 (templated cluster size).
// TCLU CTAs per cluster, each CTA owns ROWS = 4*(HID/TCLU) gate rows.
// W chunk in registers; 4-batch partial dots; smem reduce; cell update +
// DSMEM broadcast of h. TCLU=16 -> 2 co-resident clusters per SM.
// Prefetch of gx[t+1] is CLAMPED to S-1 (the R7 crash was an OOB read here).
// ---------------------------------------------------------------------------
template <int TCLU>
DI void lstm_rec_body(const float* __restrict__ Whh, const float* __restrict__ gx,
                      float* __restrict__ hs) {
    constexpr int TUPC  = HID_ / TCLU;       // units per CTA
    constexpr int TROWS = 4 * TUPC;          // gate rows per CTA
    constexpr int NKS   = NTHR / TROWS;      // k-chunks (16->8, 8->4)
    constexpr int KC    = HID_ / NKS;        // floats per chunk (32 / 64)
    constexpr int QN    = KC / 4;            // 16B loads per chunk-batch

    extern __shared__ float sm[];
    float* sH   = sm;                         // [2][BPC][HID]
    float* sRed = sm + 2 * BPC * HID_;        // [NKS][TROWS][BPC]

    const int tid  = threadIdx.x;
    const int rank = blockIdx.x % TCLU;
    const int grp  = blockIdx.x / TCLU;
    const int r    = tid % TROWS;
    const int ks   = tid / TROWS;
    const int gate = r / TUPC;
    const int u    = r % TUPC;
    const int grow = gate * HID_ + rank * TUPC + u;

    // W chunk into registers: KC floats = KC/2 packed pairs
    unsigned long long w[KC / 2];
    {
        const float4* src = (const float4*)(Whh + (size_t)grow * HID_ + ks * KC);
        #pragma unroll
        for (int i = 0; i < QN; i++) {
            float4 v = src[i];
            ulonglong2 p = *(const ulonglong2*)&v;
            w[2 * i]     = p.x;
            w[2 * i + 1] = p.y;
        }
    }

    for (int i = tid; i < 2 * BPC * HID_; i += NTHR) sH[i] = 0.f;
    __syncthreads();
    cluster_sync();

    // Update threads: tid < BPC*TUPC, unit uu, batch bb
    const int uu = tid / BPC, bb = tid % BPC;
    float c = 0.f;
    float gxn[4];
    const float* gxbase = gx + (size_t)(grp * BPC + bb) * S_ * G_ + rank * TUPC + uu;
    if (tid < BPC * TUPC) {
        #pragma unroll
        for (int g = 0; g < 4; g++) gxn[g] = __ldg(gxbase + g * HID_);
    }

    int cur = 0;
    for (int t = 0; t < S_; t++) {
        // ---- partial dots: two passes of 2 batches ----
        const float* hp = sH + cur * BPC * HID_;
        float red[4];
        #pragma unroll
        for (int bp = 0; bp < 2; bp++) {
            const ulonglong2* hA = (const ulonglong2*)(hp + (2 * bp + 0) * HID_ + ks * KC);
            const ulonglong2* hB = (const ulonglong2*)(hp + (2 * bp + 1) * HID_ + ks * KC);
            unsigned long long s0 = 0ull, s1 = 0ull, s2 = 0ull, s3 = 0ull;
            #pragma unroll
            for (int q = 0; q < QN; q++) {
                ulonglong2 xA = hA[q];
                ulonglong2 xB = hB[q];
                ffma2(s0, w[2 * q],     xA.x);
                ffma2(s1, w[2 * q + 1], xA.y);
                ffma2(s2, w[2 * q],     xB.x);
                ffma2(s3, w[2 * q + 1], xB.y);
            }
            red[2 * bp + 0] = (lo2(s0) + hi2(s0)) + (lo2(s1) + hi2(s1));
            red[2 * bp + 1] = (lo2(s2) + hi2(s2)) + (lo2(s3) + hi2(s3));
        }
        float4 pv = { red[0], red[1], red[2], red[3] };
        *(float4*)&sRed[(ks * TROWS + r) * BPC] = pv;
        __syncthreads();

        // ---- cell update ----
        if (tid < BPC * TUPC) {
            float gates[4];
            #pragma unroll
            for (int g = 0; g < 4; g++) {
                int rr = g * TUPC + uu;
                float s = gxn[g];
                #pragma unroll
                for (int k2 = 0; k2 < NKS; k2++)
                    s += sRed[(k2 * TROWS + rr) * BPC + bb];
                gates[g] = s;
            }
            {   // prefetch next gx, CLAMPED to last step (no OOB; SEL not branch)
                int tn = (t + 1 < S_) ? (t + 1) : (S_ - 1);
                const float* gp = gxbase + (size_t)tn * G_;
                #pragma unroll
                for (int g = 0; g < 4; g++) gxn[g] = __ldg(gp + g * HID_);
            }
            float gi = sigf(gates[0]);
            float gf = sigf(gates[1]);
            float gg = tanhfast(gates[2]);
            float go = sigf(gates[3]);
            c = gf * c + gi * gg;
            float h = go * tanhfast(c);

            // broadcast h to all cluster CTAs' next buffer (incl. self)
            uint32_t loc = s2u(sH + (cur ^ 1) * BPC * HID_ + bb * HID_ + rank * TUPC + uu);
            #pragma unroll
            for (int p = 0; p < TCLU; p++) {
                uint32_t rem;
                asm volatile("mapa.shared::cluster.u32 %0, %1, %2;"
                             : "=r"(rem) : "r"(loc), "r"(p));
                asm volatile("st.shared::cluster.f32 [%0], %1;"
                             :: "r"(rem), "f"(h) : "memory");
            }
            hs[((size_t)(grp * BPC + bb) * S_ + t) * HID_ + rank * TUPC + uu] = h;
        }
        cluster_sync();
        cur ^= 1;
    }
}

__global__ void __cluster_dims__(16, 1, 1) __launch_bounds__(NTHR, 2)
lstm_rec16_kernel(const float* __restrict__ Whh, const float* __restrict__ gx,
                  float* __restrict__ hs) {
    lstm_rec_body<16>(Whh, gx, hs);
}

__global__ void __cluster_dims__(8, 1, 1) __launch_bounds__(NTHR, 1)
lstm_rec8_kernel(const float* __restrict__ Whh, const float* __restrict__ gx,
                 float* __restrict__ hs) {
    lstm_rec_body<8>(Whh, gx, hs);
}

// ---------------------------------------------------------------------------
// Output projection: out[m] = dot(hs[m], W_out) + b_out  (1 warp per row)
// ---------------------------------------------------------------------------
__global__ __launch_bounds__(256) void outproj_kernel(
    const float* __restrict__ hsbuf, const float* __restrict__ Wout,
    const float* __restrict__ bout, float* __restrict__ out) {
    const long long w = ((long long)blockIdx.x * blockDim.x + threadIdx.x) >> 5;
    const int lane = threadIdx.x & 31;
    if (w >= MS) return;
    const float4* hp = (const float4*)(hsbuf + (size_t)w * HID_);
    const float4* wp = (const float4*)Wout;
    float s = 0.f;
    #pragma unroll
    for (int q = 0; q < 2; q++) {
        float4 h = hp[lane + q * 32];
        float4 ww = wp[lane + q * 32];
        s += h.x * ww.x + h.y * ww.y + h.z * ww.z + h.w * ww.w;
    }
    #pragma unroll
    for (int off = 16; off; off >>= 1) s += __shfl_xor_sync(0xFFFFFFFFu, s, off);
    if (lane == 0) out[w] = s + bout[0];
}

// ---------------------------------------------------------------------------
// Launch
// ---------------------------------------------------------------------------
extern "C" void kernel_launch(void* const* d_in, const int* in_sizes, int n_in,
                              void* d_out, int out_size) {
    const float* in_states = (const float*)d_in[0];
    const float* W_in  = (const float*)d_in[1];
    const float* b_in  = (const float*)d_in[2];
    const float* W_ih0 = (const float*)d_in[3];
    const float* W_hh0 = (const float*)d_in[4];
    const float* b_ih0 = (const float*)d_in[5];
    const float* b_hh0 = (const float*)d_in[6];
    const float* W_ih1 = (const float*)d_in[7];
    const float* W_hh1 = (const float*)d_in[8];
    const float* b_ih1 = (const float*)d_in[9];
    const float* b_hh1 = (const float*)d_in[10];
    const float* W_out = (const float*)d_in[11];
    const float* b_out = (const float*)d_in[12];
    float* out = (float*)d_out;

    float *gx = nullptr, *hsb = nullptr, *Wc = nullptr, *b0 = nullptr, *b1 = nullptr;
    cudaGetSymbolAddress((void**)&gx,  g_gx);
    cudaGetSymbolAddress((void**)&hsb, g_hs);
    cudaGetSymbolAddress((void**)&Wc,  g_Wc);
    cudaGetSymbolAddress((void**)&b0,  g_b0);
    cudaGetSymbolAddress((void**)&b1,  g_b1);

    // Prefer the 16-CTA-cluster variant (2 co-resident clusters / SM).
    bool use16 =
        (cudaFuncSetAttribute(lstm_rec16_kernel,
                              cudaFuncAttributeNonPortableClusterSizeAllowed, 1)
         == cudaSuccess);

    // 1) fused weights/biases
    prep_kernel<<<(G_ * F_ + 255) / 256, 256>>>(W_ih0, W_in, b_in, b_ih0, b_hh0, b_ih1, b_hh1);

    dim3 ggrid(G_ / 128, (unsigned)(MS / 128));   // (8, 1024)

    // 2) gx0 = in_states @ Wc^T + b0     (K = 40)
    gemm_bias_f32<<<ggrid, 256>>>(in_states, Wc, b0, gx, F_, G_);

    // keeps ncu capture slot on the recurrence kernel
    noop_kernel<<<1, 32>>>();

    // 3) layer-0 recurrence -> hs
    if (use16) lstm_rec16_kernel<<<16 * 16, NTHR, REC_SMEM>>>(W_hh0, gx, hsb);
    else       lstm_rec8_kernel<<<16 * 8,  NTHR, REC_SMEM>>>(W_hh0, gx, hsb);

    // 4) gx1 = hs @ W_ih1^T + b1        (K = 256)
    gemm_bias_f32<<<ggrid, 256>>>(hsb, W_ih1, b1, gx, HID_, G_);

    // 5) layer-1 recurrence -> hs
    if (use16) lstm_rec16_kernel<<<16 * 16, NTHR, REC_SMEM>>>(W_hh1, gx, hsb);
    else       lstm_rec8_kernel<<<16 * 8,  NTHR, REC_SMEM>>>(W_hh1, gx, hsb);

    // 6) output projection
    outproj_kernel<<<(unsigned)(MS / 8), 256>>>(hsb, W_out, b_out, out);
}